// round 10
// baseline (speedup 1.0000x reference)
#include <cuda_runtime.h>
#include <math.h>

#define BATCH   32
#define T_LEN   4096
#define CH_IN   8
#define C_RES   64
#define C_SKIP  256
#define NLAYERS 20
#define TILE_T  128
#define NTHREADS 256

// ping-pong residual buffers: 2 x 32*64*4096 floats = 2 x 33.5 MB
__device__ float g_h[2][BATCH * C_RES * T_LEN];

// ---------------------------------------------------------------------------
// Shared memory layout (floats):
//   hc  [64][128]                     @ 0      (8192)
//   zz  [64][128]                     @ 8192   (8192)
//   regionX @ 16384:
//     phase A : wf0T/wf1T/wg0T/wg1T [64][64] (4*4096) then hp [64][128] (8192)
//     phase BC: wsT [64][256] (16384), wrT [64][64] (4096)
//   total = 16384 + 24576 = 40960 floats = 160 KB
// ---------------------------------------------------------------------------
#define SMEM_FLOATS 40960
#define SMEM_BYTES  (SMEM_FLOATS * 4)

__global__ void __launch_bounds__(NTHREADS, 1)
wavenet_layer(int ping, int layer, int dil, int first,
              const float* __restrict__ w_f, const float* __restrict__ b_f,
              const float* __restrict__ w_g, const float* __restrict__ b_g,
              const float* __restrict__ w_s, const float* __restrict__ b_s,
              const float* __restrict__ w_r, const float* __restrict__ b_r,
              float* __restrict__ skip_out)
{
    extern __shared__ float sm[];
    float* hc  = sm;                 // [64][128]
    float* zz  = sm + 8192;         // [64][128]
    float* wf0 = sm + 16384;        // [ci][co]  64x64
    float* wf1 = wf0 + 4096;
    float* wg0 = wf1 + 4096;
    float* wg1 = wg0 + 4096;
    float* hp  = wg1 + 4096;        // [64][128]
    float* wsT = sm + 16384;        // [ci][cs]  64x256  (phase B/C, overlays wf/hp)
    float* wrT = wsT + 16384;       // [ci][co]  64x64

    const int tid = threadIdx.x;
    const int blk = blockIdx.x;
    const int b   = blk / (T_LEN / TILE_T);
    const int t0  = (blk % (T_LEN / TILE_T)) * TILE_T;

    const float* __restrict__ hsrc_b = &g_h[ping][0]     + b * (C_RES * T_LEN);
    float*       __restrict__ hdst_b = &g_h[ping ^ 1][0] + b * (C_RES * T_LEN);

    // ---- load current h tile (vectorized, aligned: t0 % 128 == 0) ----
    #pragma unroll
    for (int k = 0; k < 8; k++) {
        int idx = tid + k * 256;        // float4 index, 0..2047
        int c   = idx >> 5;             // 32 float4 per 128-wide row
        int t4  = idx & 31;
        reinterpret_cast<float4*>(hc)[idx] =
            *(reinterpret_cast<const float4*>(hsrc_b + c * T_LEN + t0) + t4);
    }
    // ---- load dilated-past h tile (scalar: dil may be odd) ----
    #pragma unroll
    for (int k = 0; k < 32; k++) {
        int idx = tid + k * 256;        // 0..8191
        int c   = idx >> 7;
        int tt  = idx & 127;
        int tg  = t0 + tt - dil;
        hp[idx] = (tg >= 0) ? hsrc_b[c * T_LEN + tg] : 0.0f;
    }
    // ---- load f/g weights, transposed to [ci][co] ----
    {
        const float* wfb = w_f + layer * (C_RES * C_RES * 2);
        const float* wgb = w_g + layer * (C_RES * C_RES * 2);
        #pragma unroll
        for (int k = 0; k < 16; k++) {
            int e  = tid + k * 256;     // 0..4095
            int co = e >> 6, ci = e & 63;
            float2 vf = *reinterpret_cast<const float2*>(wfb + 2 * e);
            float2 vg = *reinterpret_cast<const float2*>(wgb + 2 * e);
            wf0[ci * 64 + co] = vf.x;  wf1[ci * 64 + co] = vf.y;
            wg0[ci * 64 + co] = vg.x;  wg1[ci * 64 + co] = vg.y;
        }
    }
    __syncthreads();

    const int tx  = tid & 15;
    const int ty  = tid >> 4;
    const int c0  = ty * 4;     // 4 output channels per thread
    const int tt0 = tx * 8;     // 8 timesteps per thread

    // =================== Phase A: gated pre-activations ====================
    float fa[4][8], ga[4][8];
    #pragma unroll
    for (int u = 0; u < 4; u++) {
        float bfv = b_f[layer * C_RES + c0 + u];
        float bgv = b_g[layer * C_RES + c0 + u];
        #pragma unroll
        for (int v = 0; v < 8; v++) { fa[u][v] = bfv; ga[u][v] = bgv; }
    }

    #pragma unroll 2
    for (int ci = 0; ci < 64; ci++) {
        float4 wA0 = *reinterpret_cast<float4*>(wf0 + ci * 64 + c0);
        float4 wA1 = *reinterpret_cast<float4*>(wf1 + ci * 64 + c0);
        float4 wB0 = *reinterpret_cast<float4*>(wg0 + ci * 64 + c0);
        float4 wB1 = *reinterpret_cast<float4*>(wg1 + ci * 64 + c0);
        float4 p0  = *reinterpret_cast<float4*>(hp + ci * 128 + tt0);
        float4 p1  = *reinterpret_cast<float4*>(hp + ci * 128 + tt0 + 4);
        float4 q0  = *reinterpret_cast<float4*>(hc + ci * 128 + tt0);
        float4 q1  = *reinterpret_cast<float4*>(hc + ci * 128 + tt0 + 4);

        float wf0v[4] = {wA0.x, wA0.y, wA0.z, wA0.w};
        float wf1v[4] = {wA1.x, wA1.y, wA1.z, wA1.w};
        float wg0v[4] = {wB0.x, wB0.y, wB0.z, wB0.w};
        float wg1v[4] = {wB1.x, wB1.y, wB1.z, wB1.w};
        float pv[8]   = {p0.x, p0.y, p0.z, p0.w, p1.x, p1.y, p1.z, p1.w};
        float cv[8]   = {q0.x, q0.y, q0.z, q0.w, q1.x, q1.y, q1.z, q1.w};

        #pragma unroll
        for (int u = 0; u < 4; u++)
            #pragma unroll
            for (int v = 0; v < 8; v++) {
                fa[u][v] = fmaf(wf0v[u], pv[v], fa[u][v]);
                fa[u][v] = fmaf(wf1v[u], cv[v], fa[u][v]);
                ga[u][v] = fmaf(wg0v[u], pv[v], ga[u][v]);
                ga[u][v] = fmaf(wg1v[u], cv[v], ga[u][v]);
            }
    }

    // ---- activations: z = tanh(f) * sigmoid(g) ----
    #pragma unroll
    for (int u = 0; u < 4; u++) {
        #pragma unroll
        for (int v = 0; v < 8; v++) {
            float f = fa[u][v], g = ga[u][v];
            float th = __fdividef(2.0f, 1.0f + __expf(-2.0f * f)) - 1.0f;
            float sg = __fdividef(1.0f, 1.0f + __expf(-g));
            fa[u][v] = th * sg;
        }
        float4 s0 = make_float4(fa[u][0], fa[u][1], fa[u][2], fa[u][3]);
        float4 s1 = make_float4(fa[u][4], fa[u][5], fa[u][6], fa[u][7]);
        *reinterpret_cast<float4*>(zz + (c0 + u) * 128 + tt0)     = s0;
        *reinterpret_cast<float4*>(zz + (c0 + u) * 128 + tt0 + 4) = s1;
    }
    __syncthreads();   // zz published; regionX reads done

    // ---- load skip / res weights, transposed ----
    {
        const float* wsb = w_s + layer * (C_SKIP * C_RES);
        #pragma unroll
        for (int k = 0; k < 64; k++) {
            int e  = tid + k * 256;     // 0..16383
            int cs = e >> 6, ci = e & 63;
            wsT[ci * 256 + cs] = wsb[e];
        }
        const float* wrb = w_r + layer * (C_RES * C_RES);
        #pragma unroll
        for (int k = 0; k < 16; k++) {
            int e  = tid + k * 256;
            int co = e >> 6, ci = e & 63;
            wrT[ci * 64 + co] = wrb[e];
        }
    }
    __syncthreads();

    // =================== Phase B: skip accumulation =========================
    #pragma unroll 1
    for (int q = 0; q < 4; q++) {
        const int cs0 = q * 64 + c0;
        float acc[4][8];
        #pragma unroll
        for (int u = 0; u < 4; u++) {
            float bsv = b_s[layer * C_SKIP + cs0 + u];
            #pragma unroll
            for (int v = 0; v < 8; v++) acc[u][v] = bsv;
        }
        #pragma unroll 2
        for (int ci = 0; ci < 64; ci++) {
            float4 wv = *reinterpret_cast<float4*>(wsT + ci * 256 + cs0);
            float4 z0 = *reinterpret_cast<float4*>(zz + ci * 128 + tt0);
            float4 z1 = *reinterpret_cast<float4*>(zz + ci * 128 + tt0 + 4);
            float wa[4] = {wv.x, wv.y, wv.z, wv.w};
            float zv[8] = {z0.x, z0.y, z0.z, z0.w, z1.x, z1.y, z1.z, z1.w};
            #pragma unroll
            for (int u = 0; u < 4; u++)
                #pragma unroll
                for (int v = 0; v < 8; v++)
                    acc[u][v] = fmaf(wa[u], zv[v], acc[u][v]);
        }
        #pragma unroll
        for (int u = 0; u < 4; u++) {
            float* op = skip_out + ((size_t)b * C_SKIP + cs0 + u) * T_LEN + t0 + tt0;
            float4 a0 = make_float4(acc[u][0], acc[u][1], acc[u][2], acc[u][3]);
            float4 a1 = make_float4(acc[u][4], acc[u][5], acc[u][6], acc[u][7]);
            if (first) {
                *reinterpret_cast<float4*>(op)     = a0;
                *reinterpret_cast<float4*>(op + 4) = a1;
            } else {
                float4 o0 = *reinterpret_cast<const float4*>(op);
                float4 o1 = *reinterpret_cast<const float4*>(op + 4);
                o0.x += a0.x; o0.y += a0.y; o0.z += a0.z; o0.w += a0.w;
                o1.x += a1.x; o1.y += a1.y; o1.z += a1.z; o1.w += a1.w;
                *reinterpret_cast<float4*>(op)     = o0;
                *reinterpret_cast<float4*>(op + 4) = o1;
            }
        }
    }

    // =================== Phase C: residual ==================================
    {
        float acc[4][8];
        #pragma unroll
        for (int u = 0; u < 4; u++) {
            float brv = b_r[layer * C_RES + c0 + u];
            #pragma unroll
            for (int v = 0; v < 8; v++) acc[u][v] = brv;
        }
        #pragma unroll 2
        for (int ci = 0; ci < 64; ci++) {
            float4 wv = *reinterpret_cast<float4*>(wrT + ci * 64 + c0);
            float4 z0 = *reinterpret_cast<float4*>(zz + ci * 128 + tt0);
            float4 z1 = *reinterpret_cast<float4*>(zz + ci * 128 + tt0 + 4);
            float wa[4] = {wv.x, wv.y, wv.z, wv.w};
            float zv[8] = {z0.x, z0.y, z0.z, z0.w, z1.x, z1.y, z1.z, z1.w};
            #pragma unroll
            for (int u = 0; u < 4; u++)
                #pragma unroll
                for (int v = 0; v < 8; v++)
                    acc[u][v] = fmaf(wa[u], zv[v], acc[u][v]);
        }
        #pragma unroll
        for (int u = 0; u < 4; u++) {
            float4 r0 = *reinterpret_cast<float4*>(hc + (c0 + u) * 128 + tt0);
            float4 r1 = *reinterpret_cast<float4*>(hc + (c0 + u) * 128 + tt0 + 4);
            float4 a0 = make_float4(acc[u][0] + r0.x, acc[u][1] + r0.y,
                                    acc[u][2] + r0.z, acc[u][3] + r0.w);
            float4 a1 = make_float4(acc[u][4] + r1.x, acc[u][5] + r1.y,
                                    acc[u][6] + r1.z, acc[u][7] + r1.w);
            float* op = hdst_b + (c0 + u) * T_LEN + t0 + tt0;
            *reinterpret_cast<float4*>(op)     = a0;
            *reinterpret_cast<float4*>(op + 4) = a1;
        }
    }
}

// ---------------------------------------------------------------------------
// input 1x1 conv: h0[b,co,t] = b_in[co] + sum_ci w_in[co,ci] * x[b,ci,t]
// ---------------------------------------------------------------------------
__global__ void __launch_bounds__(256)
input_conv(const float* __restrict__ x, const float* __restrict__ w_in,
           const float* __restrict__ b_in)
{
    int gid = blockIdx.x * blockDim.x + threadIdx.x;   // 0 .. B*T-1
    int b = gid >> 12;          // T = 4096
    int t = gid & 4095;
    float xv[CH_IN];
    #pragma unroll
    for (int ci = 0; ci < CH_IN; ci++)
        xv[ci] = x[((size_t)b * CH_IN + ci) * T_LEN + t];
    float* h0 = &g_h[0][0] + (size_t)b * C_RES * T_LEN + t;
    #pragma unroll
    for (int co = 0; co < C_RES; co++) {
        float acc = __ldg(b_in + co);
        #pragma unroll
        for (int ci = 0; ci < CH_IN; ci++)
            acc = fmaf(__ldg(w_in + co * CH_IN + ci), xv[ci], acc);
        h0[(size_t)co * T_LEN] = acc;
    }
}

extern "C" void kernel_launch(void* const* d_in, const int* in_sizes, int n_in,
                              void* d_out, int out_size)
{
    (void)in_sizes; (void)n_in; (void)out_size;
    const float* x    = (const float*)d_in[0];
    const float* w_in = (const float*)d_in[1];
    const float* b_in = (const float*)d_in[2];
    const float* w_f  = (const float*)d_in[3];
    const float* b_f  = (const float*)d_in[4];
    const float* w_g  = (const float*)d_in[5];
    const float* b_g  = (const float*)d_in[6];
    const float* w_s  = (const float*)d_in[7];
    const float* b_s  = (const float*)d_in[8];
    const float* w_r  = (const float*)d_in[9];
    const float* b_r  = (const float*)d_in[10];
    float* skip = (float*)d_out;

    cudaFuncSetAttribute(wavenet_layer,
                         cudaFuncAttributeMaxDynamicSharedMemorySize, SMEM_BYTES);

    input_conv<<<(BATCH * T_LEN) / 256, 256>>>(x, w_in, b_in);

    for (int i = 0; i < NLAYERS; i++) {
        int dil = 1 << (i % 10);
        wavenet_layer<<<BATCH * (T_LEN / TILE_T), NTHREADS, SMEM_BYTES>>>(
            i & 1, i, dil, (i == 0) ? 1 : 0,
            w_f, b_f, w_g, b_g, w_s, b_s, w_r, b_r, skip);
    }
}

// round 11
// speedup vs baseline: 1.0007x; 1.0007x over previous
#include <cuda_runtime.h>
#include <math.h>

#define BATCH   32
#define T_LEN   4096
#define CH_IN   8
#define C_RES   64
#define C_SKIP  256
#define NLAYERS 20
#define TILE_T  128
#define NTHREADS 256

// ping-pong residual buffers: 2 x 32*64*4096 floats = 2 x 33.5 MB
__device__ float g_h[2][BATCH * C_RES * T_LEN];

// ---------------------------------------------------------------------------
// Shared memory layout (floats):
//   hc  [64][128]                     @ 0      (8192)
//   zz  [64][128]                     @ 8192   (8192)
//   regionX @ 16384:
//     phase A : wf0T/wf1T/wg0T/wg1T [64][64] (4*4096) then hp [64][128] (8192)
//     phase BC: wsT [64][256] (16384), wrT [64][64] (4096)
//   total = 16384 + 24576 = 40960 floats = 160 KB
// ---------------------------------------------------------------------------
#define SMEM_FLOATS 40960
#define SMEM_BYTES  (SMEM_FLOATS * 4)

__global__ void __launch_bounds__(NTHREADS, 1)
wavenet_layer(int ping, int layer, int dil, int first,
              const float* __restrict__ w_f, const float* __restrict__ b_f,
              const float* __restrict__ w_g, const float* __restrict__ b_g,
              const float* __restrict__ w_s, const float* __restrict__ b_s,
              const float* __restrict__ w_r, const float* __restrict__ b_r,
              float* __restrict__ skip_out)
{
    extern __shared__ float sm[];
    float* hc  = sm;                 // [64][128]
    float* zz  = sm + 8192;         // [64][128]
    float* wf0 = sm + 16384;        // [ci][co]  64x64
    float* wf1 = wf0 + 4096;
    float* wg0 = wf1 + 4096;
    float* wg1 = wg0 + 4096;
    float* hp  = wg1 + 4096;        // [64][128]
    float* wsT = sm + 16384;        // [ci][cs]  64x256  (phase B/C, overlays wf/hp)
    float* wrT = wsT + 16384;       // [ci][co]  64x64

    const int tid = threadIdx.x;
    const int blk = blockIdx.x;
    const int b   = blk / (T_LEN / TILE_T);
    const int t0  = (blk % (T_LEN / TILE_T)) * TILE_T;

    const float* __restrict__ hsrc_b = &g_h[ping][0]     + b * (C_RES * T_LEN);
    float*       __restrict__ hdst_b = &g_h[ping ^ 1][0] + b * (C_RES * T_LEN);

    // ---- load current h tile (vectorized, aligned: t0 % 128 == 0) ----
    #pragma unroll
    for (int k = 0; k < 8; k++) {
        int idx = tid + k * 256;        // float4 index, 0..2047
        int c   = idx >> 5;             // 32 float4 per 128-wide row
        int t4  = idx & 31;
        reinterpret_cast<float4*>(hc)[idx] =
            *(reinterpret_cast<const float4*>(hsrc_b + c * T_LEN + t0) + t4);
    }
    // ---- load dilated-past h tile (scalar: dil may be odd) ----
    #pragma unroll
    for (int k = 0; k < 32; k++) {
        int idx = tid + k * 256;        // 0..8191
        int c   = idx >> 7;
        int tt  = idx & 127;
        int tg  = t0 + tt - dil;
        hp[idx] = (tg >= 0) ? hsrc_b[c * T_LEN + tg] : 0.0f;
    }
    // ---- load f/g weights, transposed to [ci][co] ----
    {
        const float* wfb = w_f + layer * (C_RES * C_RES * 2);
        const float* wgb = w_g + layer * (C_RES * C_RES * 2);
        #pragma unroll
        for (int k = 0; k < 16; k++) {
            int e  = tid + k * 256;     // 0..4095
            int co = e >> 6, ci = e & 63;
            float2 vf = *reinterpret_cast<const float2*>(wfb + 2 * e);
            float2 vg = *reinterpret_cast<const float2*>(wgb + 2 * e);
            wf0[ci * 64 + co] = vf.x;  wf1[ci * 64 + co] = vf.y;
            wg0[ci * 64 + co] = vg.x;  wg1[ci * 64 + co] = vg.y;
        }
    }
    __syncthreads();

    const int tx  = tid & 15;
    const int ty  = tid >> 4;
    const int c0  = ty * 4;     // 4 output channels per thread
    const int tt0 = tx * 8;     // 8 timesteps per thread

    // =================== Phase A: gated pre-activations ====================
    float fa[4][8], ga[4][8];
    #pragma unroll
    for (int u = 0; u < 4; u++) {
        float bfv = b_f[layer * C_RES + c0 + u];
        float bgv = b_g[layer * C_RES + c0 + u];
        #pragma unroll
        for (int v = 0; v < 8; v++) { fa[u][v] = bfv; ga[u][v] = bgv; }
    }

    #pragma unroll 2
    for (int ci = 0; ci < 64; ci++) {
        float4 wA0 = *reinterpret_cast<float4*>(wf0 + ci * 64 + c0);
        float4 wA1 = *reinterpret_cast<float4*>(wf1 + ci * 64 + c0);
        float4 wB0 = *reinterpret_cast<float4*>(wg0 + ci * 64 + c0);
        float4 wB1 = *reinterpret_cast<float4*>(wg1 + ci * 64 + c0);
        float4 p0  = *reinterpret_cast<float4*>(hp + ci * 128 + tt0);
        float4 p1  = *reinterpret_cast<float4*>(hp + ci * 128 + tt0 + 4);
        float4 q0  = *reinterpret_cast<float4*>(hc + ci * 128 + tt0);
        float4 q1  = *reinterpret_cast<float4*>(hc + ci * 128 + tt0 + 4);

        float wf0v[4] = {wA0.x, wA0.y, wA0.z, wA0.w};
        float wf1v[4] = {wA1.x, wA1.y, wA1.z, wA1.w};
        float wg0v[4] = {wB0.x, wB0.y, wB0.z, wB0.w};
        float wg1v[4] = {wB1.x, wB1.y, wB1.z, wB1.w};
        float pv[8]   = {p0.x, p0.y, p0.z, p0.w, p1.x, p1.y, p1.z, p1.w};
        float cv[8]   = {q0.x, q0.y, q0.z, q0.w, q1.x, q1.y, q1.z, q1.w};

        #pragma unroll
        for (int u = 0; u < 4; u++)
            #pragma unroll
            for (int v = 0; v < 8; v++) {
                fa[u][v] = fmaf(wf0v[u], pv[v], fa[u][v]);
                fa[u][v] = fmaf(wf1v[u], cv[v], fa[u][v]);
                ga[u][v] = fmaf(wg0v[u], pv[v], ga[u][v]);
                ga[u][v] = fmaf(wg1v[u], cv[v], ga[u][v]);
            }
    }

    // ---- activations: z = tanh(f) * sigmoid(g) ----
    #pragma unroll
    for (int u = 0; u < 4; u++) {
        #pragma unroll
        for (int v = 0; v < 8; v++) {
            float f = fa[u][v], g = ga[u][v];
            float th = __fdividef(2.0f, 1.0f + __expf(-2.0f * f)) - 1.0f;
            float sg = __fdividef(1.0f, 1.0f + __expf(-g));
            fa[u][v] = th * sg;
        }
        float4 s0 = make_float4(fa[u][0], fa[u][1], fa[u][2], fa[u][3]);
        float4 s1 = make_float4(fa[u][4], fa[u][5], fa[u][6], fa[u][7]);
        *reinterpret_cast<float4*>(zz + (c0 + u) * 128 + tt0)     = s0;
        *reinterpret_cast<float4*>(zz + (c0 + u) * 128 + tt0 + 4) = s1;
    }
    __syncthreads();   // zz published; regionX reads done

    // ---- load skip / res weights, transposed ----
    {
        const float* wsb = w_s + layer * (C_SKIP * C_RES);
        #pragma unroll
        for (int k = 0; k < 64; k++) {
            int e  = tid + k * 256;     // 0..16383
            int cs = e >> 6, ci = e & 63;
            wsT[ci * 256 + cs] = wsb[e];
        }
        const float* wrb = w_r + layer * (C_RES * C_RES);
        #pragma unroll
        for (int k = 0; k < 16; k++) {
            int e  = tid + k * 256;
            int co = e >> 6, ci = e & 63;
            wrT[ci * 64 + co] = wrb[e];
        }
    }
    __syncthreads();

    // =================== Phase B: skip accumulation =========================
    #pragma unroll 1
    for (int q = 0; q < 4; q++) {
        const int cs0 = q * 64 + c0;
        float acc[4][8];
        #pragma unroll
        for (int u = 0; u < 4; u++) {
            float bsv = b_s[layer * C_SKIP + cs0 + u];
            #pragma unroll
            for (int v = 0; v < 8; v++) acc[u][v] = bsv;
        }
        #pragma unroll 2
        for (int ci = 0; ci < 64; ci++) {
            float4 wv = *reinterpret_cast<float4*>(wsT + ci * 256 + cs0);
            float4 z0 = *reinterpret_cast<float4*>(zz + ci * 128 + tt0);
            float4 z1 = *reinterpret_cast<float4*>(zz + ci * 128 + tt0 + 4);
            float wa[4] = {wv.x, wv.y, wv.z, wv.w};
            float zv[8] = {z0.x, z0.y, z0.z, z0.w, z1.x, z1.y, z1.z, z1.w};
            #pragma unroll
            for (int u = 0; u < 4; u++)
                #pragma unroll
                for (int v = 0; v < 8; v++)
                    acc[u][v] = fmaf(wa[u], zv[v], acc[u][v]);
        }
        #pragma unroll
        for (int u = 0; u < 4; u++) {
            float* op = skip_out + ((size_t)b * C_SKIP + cs0 + u) * T_LEN + t0 + tt0;
            float4 a0 = make_float4(acc[u][0], acc[u][1], acc[u][2], acc[u][3]);
            float4 a1 = make_float4(acc[u][4], acc[u][5], acc[u][6], acc[u][7]);
            if (first) {
                *reinterpret_cast<float4*>(op)     = a0;
                *reinterpret_cast<float4*>(op + 4) = a1;
            } else {
                float4 o0 = *reinterpret_cast<const float4*>(op);
                float4 o1 = *reinterpret_cast<const float4*>(op + 4);
                o0.x += a0.x; o0.y += a0.y; o0.z += a0.z; o0.w += a0.w;
                o1.x += a1.x; o1.y += a1.y; o1.z += a1.z; o1.w += a1.w;
                *reinterpret_cast<float4*>(op)     = o0;
                *reinterpret_cast<float4*>(op + 4) = o1;
            }
        }
    }

    // =================== Phase C: residual ==================================
    {
        float acc[4][8];
        #pragma unroll
        for (int u = 0; u < 4; u++) {
            float brv = b_r[layer * C_RES + c0 + u];
            #pragma unroll
            for (int v = 0; v < 8; v++) acc[u][v] = brv;
        }
        #pragma unroll 2
        for (int ci = 0; ci < 64; ci++) {
            float4 wv = *reinterpret_cast<float4*>(wrT + ci * 64 + c0);
            float4 z0 = *reinterpret_cast<float4*>(zz + ci * 128 + tt0);
            float4 z1 = *reinterpret_cast<float4*>(zz + ci * 128 + tt0 + 4);
            float wa[4] = {wv.x, wv.y, wv.z, wv.w};
            float zv[8] = {z0.x, z0.y, z0.z, z0.w, z1.x, z1.y, z1.z, z1.w};
            #pragma unroll
            for (int u = 0; u < 4; u++)
                #pragma unroll
                for (int v = 0; v < 8; v++)
                    acc[u][v] = fmaf(wa[u], zv[v], acc[u][v]);
        }
        #pragma unroll
        for (int u = 0; u < 4; u++) {
            float4 r0 = *reinterpret_cast<float4*>(hc + (c0 + u) * 128 + tt0);
            float4 r1 = *reinterpret_cast<float4*>(hc + (c0 + u) * 128 + tt0 + 4);
            float4 a0 = make_float4(acc[u][0] + r0.x, acc[u][1] + r0.y,
                                    acc[u][2] + r0.z, acc[u][3] + r0.w);
            float4 a1 = make_float4(acc[u][4] + r1.x, acc[u][5] + r1.y,
                                    acc[u][6] + r1.z, acc[u][7] + r1.w);
            float* op = hdst_b + (c0 + u) * T_LEN + t0 + tt0;
            *reinterpret_cast<float4*>(op)     = a0;
            *reinterpret_cast<float4*>(op + 4) = a1;
        }
    }
}

// ---------------------------------------------------------------------------
// input 1x1 conv: h0[b,co,t] = b_in[co] + sum_ci w_in[co,ci] * x[b,ci,t]
// ---------------------------------------------------------------------------
__global__ void __launch_bounds__(256)
input_conv(const float* __restrict__ x, const float* __restrict__ w_in,
           const float* __restrict__ b_in)
{
    int gid = blockIdx.x * blockDim.x + threadIdx.x;   // 0 .. B*T-1
    int b = gid >> 12;          // T = 4096
    int t = gid & 4095;
    float xv[CH_IN];
    #pragma unroll
    for (int ci = 0; ci < CH_IN; ci++)
        xv[ci] = x[((size_t)b * CH_IN + ci) * T_LEN + t];
    float* h0 = &g_h[0][0] + (size_t)b * C_RES * T_LEN + t;
    #pragma unroll
    for (int co = 0; co < C_RES; co++) {
        float acc = __ldg(b_in + co);
        #pragma unroll
        for (int ci = 0; ci < CH_IN; ci++)
            acc = fmaf(__ldg(w_in + co * CH_IN + ci), xv[ci], acc);
        h0[(size_t)co * T_LEN] = acc;
    }
}

extern "C" void kernel_launch(void* const* d_in, const int* in_sizes, int n_in,
                              void* d_out, int out_size)
{
    (void)in_sizes; (void)n_in; (void)out_size;
    const float* x    = (const float*)d_in[0];
    const float* w_in = (const float*)d_in[1];
    const float* b_in = (const float*)d_in[2];
    const float* w_f  = (const float*)d_in[3];
    const float* b_f  = (const float*)d_in[4];
    const float* w_g  = (const float*)d_in[5];
    const float* b_g  = (const float*)d_in[6];
    const float* w_s  = (const float*)d_in[7];
    const float* b_s  = (const float*)d_in[8];
    const float* w_r  = (const float*)d_in[9];
    const float* b_r  = (const float*)d_in[10];
    float* skip = (float*)d_out;

    cudaFuncSetAttribute(wavenet_layer,
                         cudaFuncAttributeMaxDynamicSharedMemorySize, SMEM_BYTES);

    input_conv<<<(BATCH * T_LEN) / 256, 256>>>(x, w_in, b_in);

    for (int i = 0; i < NLAYERS; i++) {
        int dil = 1 << (i % 10);
        wavenet_layer<<<BATCH * (T_LEN / TILE_T), NTHREADS, SMEM_BYTES>>>(
            i & 1, i, dil, (i == 0) ? 1 : 0,
            w_f, b_f, w_g, b_g, w_s, b_s, w_r, b_r, skip);
    }
}

// round 12
// speedup vs baseline: 1.0037x; 1.0030x over previous
#include <cuda_runtime.h>
#include <math.h>

#define BATCH   32
#define T_LEN   4096
#define CH_IN   8
#define C_RES   64
#define C_SKIP  256
#define NLAYERS 20
#define TILE_T  128
#define NTHREADS 256

// ping-pong residual buffers: 2 x 32*64*4096 floats = 2 x 33.5 MB
__device__ float g_h[2][BATCH * C_RES * T_LEN];

// ---------------------------------------------------------------------------
// Shared memory layout (floats):
//   hc  [64][128]                     @ 0      (8192)
//   zz  [64][128]                     @ 8192   (8192)
//   regionX @ 16384:
//     phase A : wf0T/wf1T/wg0T/wg1T [64][64] (4*4096) then hp [64][128] (8192)
//     phase BC: wsT [64][256] (16384), wrT [64][64] (4096)
//   total = 16384 + 24576 = 40960 floats = 160 KB
// ---------------------------------------------------------------------------
#define SMEM_FLOATS 40960
#define SMEM_BYTES  (SMEM_FLOATS * 4)

__global__ void __launch_bounds__(NTHREADS, 1)
wavenet_layer(int ping, int layer, int dil, int first,
              const float* __restrict__ w_f, const float* __restrict__ b_f,
              const float* __restrict__ w_g, const float* __restrict__ b_g,
              const float* __restrict__ w_s, const float* __restrict__ b_s,
              const float* __restrict__ w_r, const float* __restrict__ b_r,
              float* __restrict__ skip_out)
{
    extern __shared__ float sm[];
    float* hc  = sm;                 // [64][128]
    float* zz  = sm + 8192;         // [64][128]
    float* wf0 = sm + 16384;        // [ci][co]  64x64
    float* wf1 = wf0 + 4096;
    float* wg0 = wf1 + 4096;
    float* wg1 = wg0 + 4096;
    float* hp  = wg1 + 4096;        // [64][128]
    float* wsT = sm + 16384;        // [ci][cs]  64x256  (phase B/C, overlays wf/hp)
    float* wrT = wsT + 16384;       // [ci][co]  64x64

    const int tid = threadIdx.x;
    const int blk = blockIdx.x;
    const int b   = blk / (T_LEN / TILE_T);
    const int t0  = (blk % (T_LEN / TILE_T)) * TILE_T;

    const float* __restrict__ hsrc_b = &g_h[ping][0]     + b * (C_RES * T_LEN);
    float*       __restrict__ hdst_b = &g_h[ping ^ 1][0] + b * (C_RES * T_LEN);

    // ---- load current h tile (vectorized, aligned: t0 % 128 == 0) ----
    #pragma unroll
    for (int k = 0; k < 8; k++) {
        int idx = tid + k * 256;        // float4 index, 0..2047
        int c   = idx >> 5;             // 32 float4 per 128-wide row
        int t4  = idx & 31;
        reinterpret_cast<float4*>(hc)[idx] =
            *(reinterpret_cast<const float4*>(hsrc_b + c * T_LEN + t0) + t4);
    }
    // ---- load dilated-past h tile (scalar: dil may be odd) ----
    #pragma unroll
    for (int k = 0; k < 32; k++) {
        int idx = tid + k * 256;        // 0..8191
        int c   = idx >> 7;
        int tt  = idx & 127;
        int tg  = t0 + tt - dil;
        hp[idx] = (tg >= 0) ? hsrc_b[c * T_LEN + tg] : 0.0f;
    }
    // ---- load f/g weights, transposed to [ci][co] ----
    {
        const float* wfb = w_f + layer * (C_RES * C_RES * 2);
        const float* wgb = w_g + layer * (C_RES * C_RES * 2);
        #pragma unroll
        for (int k = 0; k < 16; k++) {
            int e  = tid + k * 256;     // 0..4095
            int co = e >> 6, ci = e & 63;
            float2 vf = *reinterpret_cast<const float2*>(wfb + 2 * e);
            float2 vg = *reinterpret_cast<const float2*>(wgb + 2 * e);
            wf0[ci * 64 + co] = vf.x;  wf1[ci * 64 + co] = vf.y;
            wg0[ci * 64 + co] = vg.x;  wg1[ci * 64 + co] = vg.y;
        }
    }
    __syncthreads();

    const int tx  = tid & 15;
    const int ty  = tid >> 4;
    const int c0  = ty * 4;     // 4 output channels per thread
    const int tt0 = tx * 8;     // 8 timesteps per thread

    // =================== Phase A: gated pre-activations ====================
    float fa[4][8], ga[4][8];
    #pragma unroll
    for (int u = 0; u < 4; u++) {
        float bfv = b_f[layer * C_RES + c0 + u];
        float bgv = b_g[layer * C_RES + c0 + u];
        #pragma unroll
        for (int v = 0; v < 8; v++) { fa[u][v] = bfv; ga[u][v] = bgv; }
    }

    #pragma unroll 2
    for (int ci = 0; ci < 64; ci++) {
        float4 wA0 = *reinterpret_cast<float4*>(wf0 + ci * 64 + c0);
        float4 wA1 = *reinterpret_cast<float4*>(wf1 + ci * 64 + c0);
        float4 wB0 = *reinterpret_cast<float4*>(wg0 + ci * 64 + c0);
        float4 wB1 = *reinterpret_cast<float4*>(wg1 + ci * 64 + c0);
        float4 p0  = *reinterpret_cast<float4*>(hp + ci * 128 + tt0);
        float4 p1  = *reinterpret_cast<float4*>(hp + ci * 128 + tt0 + 4);
        float4 q0  = *reinterpret_cast<float4*>(hc + ci * 128 + tt0);
        float4 q1  = *reinterpret_cast<float4*>(hc + ci * 128 + tt0 + 4);

        float wf0v[4] = {wA0.x, wA0.y, wA0.z, wA0.w};
        float wf1v[4] = {wA1.x, wA1.y, wA1.z, wA1.w};
        float wg0v[4] = {wB0.x, wB0.y, wB0.z, wB0.w};
        float wg1v[4] = {wB1.x, wB1.y, wB1.z, wB1.w};
        float pv[8]   = {p0.x, p0.y, p0.z, p0.w, p1.x, p1.y, p1.z, p1.w};
        float cv[8]   = {q0.x, q0.y, q0.z, q0.w, q1.x, q1.y, q1.z, q1.w};

        #pragma unroll
        for (int u = 0; u < 4; u++)
            #pragma unroll
            for (int v = 0; v < 8; v++) {
                fa[u][v] = fmaf(wf0v[u], pv[v], fa[u][v]);
                fa[u][v] = fmaf(wf1v[u], cv[v], fa[u][v]);
                ga[u][v] = fmaf(wg0v[u], pv[v], ga[u][v]);
                ga[u][v] = fmaf(wg1v[u], cv[v], ga[u][v]);
            }
    }

    // ---- activations: z = tanh(f) * sigmoid(g) ----
    #pragma unroll
    for (int u = 0; u < 4; u++) {
        #pragma unroll
        for (int v = 0; v < 8; v++) {
            float f = fa[u][v], g = ga[u][v];
            float th = __fdividef(2.0f, 1.0f + __expf(-2.0f * f)) - 1.0f;
            float sg = __fdividef(1.0f, 1.0f + __expf(-g));
            fa[u][v] = th * sg;
        }
        float4 s0 = make_float4(fa[u][0], fa[u][1], fa[u][2], fa[u][3]);
        float4 s1 = make_float4(fa[u][4], fa[u][5], fa[u][6], fa[u][7]);
        *reinterpret_cast<float4*>(zz + (c0 + u) * 128 + tt0)     = s0;
        *reinterpret_cast<float4*>(zz + (c0 + u) * 128 + tt0 + 4) = s1;
    }
    __syncthreads();   // zz published; regionX reads done

    // ---- load skip / res weights, transposed ----
    {
        const float* wsb = w_s + layer * (C_SKIP * C_RES);
        #pragma unroll
        for (int k = 0; k < 64; k++) {
            int e  = tid + k * 256;     // 0..16383
            int cs = e >> 6, ci = e & 63;
            wsT[ci * 256 + cs] = wsb[e];
        }
        const float* wrb = w_r + layer * (C_RES * C_RES);
        #pragma unroll
        for (int k = 0; k < 16; k++) {
            int e  = tid + k * 256;
            int co = e >> 6, ci = e & 63;
            wrT[ci * 64 + co] = wrb[e];
        }
    }
    __syncthreads();

    // =================== Phase B: skip accumulation =========================
    #pragma unroll 1
    for (int q = 0; q < 4; q++) {
        const int cs0 = q * 64 + c0;
        float acc[4][8];
        #pragma unroll
        for (int u = 0; u < 4; u++) {
            float bsv = b_s[layer * C_SKIP + cs0 + u];
            #pragma unroll
            for (int v = 0; v < 8; v++) acc[u][v] = bsv;
        }
        #pragma unroll 2
        for (int ci = 0; ci < 64; ci++) {
            float4 wv = *reinterpret_cast<float4*>(wsT + ci * 256 + cs0);
            float4 z0 = *reinterpret_cast<float4*>(zz + ci * 128 + tt0);
            float4 z1 = *reinterpret_cast<float4*>(zz + ci * 128 + tt0 + 4);
            float wa[4] = {wv.x, wv.y, wv.z, wv.w};
            float zv[8] = {z0.x, z0.y, z0.z, z0.w, z1.x, z1.y, z1.z, z1.w};
            #pragma unroll
            for (int u = 0; u < 4; u++)
                #pragma unroll
                for (int v = 0; v < 8; v++)
                    acc[u][v] = fmaf(wa[u], zv[v], acc[u][v]);
        }
        #pragma unroll
        for (int u = 0; u < 4; u++) {
            float* op = skip_out + ((size_t)b * C_SKIP + cs0 + u) * T_LEN + t0 + tt0;
            float4 a0 = make_float4(acc[u][0], acc[u][1], acc[u][2], acc[u][3]);
            float4 a1 = make_float4(acc[u][4], acc[u][5], acc[u][6], acc[u][7]);
            if (first) {
                *reinterpret_cast<float4*>(op)     = a0;
                *reinterpret_cast<float4*>(op + 4) = a1;
            } else {
                float4 o0 = *reinterpret_cast<const float4*>(op);
                float4 o1 = *reinterpret_cast<const float4*>(op + 4);
                o0.x += a0.x; o0.y += a0.y; o0.z += a0.z; o0.w += a0.w;
                o1.x += a1.x; o1.y += a1.y; o1.z += a1.z; o1.w += a1.w;
                *reinterpret_cast<float4*>(op)     = o0;
                *reinterpret_cast<float4*>(op + 4) = o1;
            }
        }
    }

    // =================== Phase C: residual ==================================
    {
        float acc[4][8];
        #pragma unroll
        for (int u = 0; u < 4; u++) {
            float brv = b_r[layer * C_RES + c0 + u];
            #pragma unroll
            for (int v = 0; v < 8; v++) acc[u][v] = brv;
        }
        #pragma unroll 2
        for (int ci = 0; ci < 64; ci++) {
            float4 wv = *reinterpret_cast<float4*>(wrT + ci * 64 + c0);
            float4 z0 = *reinterpret_cast<float4*>(zz + ci * 128 + tt0);
            float4 z1 = *reinterpret_cast<float4*>(zz + ci * 128 + tt0 + 4);
            float wa[4] = {wv.x, wv.y, wv.z, wv.w};
            float zv[8] = {z0.x, z0.y, z0.z, z0.w, z1.x, z1.y, z1.z, z1.w};
            #pragma unroll
            for (int u = 0; u < 4; u++)
                #pragma unroll
                for (int v = 0; v < 8; v++)
                    acc[u][v] = fmaf(wa[u], zv[v], acc[u][v]);
        }
        #pragma unroll
        for (int u = 0; u < 4; u++) {
            float4 r0 = *reinterpret_cast<float4*>(hc + (c0 + u) * 128 + tt0);
            float4 r1 = *reinterpret_cast<float4*>(hc + (c0 + u) * 128 + tt0 + 4);
            float4 a0 = make_float4(acc[u][0] + r0.x, acc[u][1] + r0.y,
                                    acc[u][2] + r0.z, acc[u][3] + r0.w);
            float4 a1 = make_float4(acc[u][4] + r1.x, acc[u][5] + r1.y,
                                    acc[u][6] + r1.z, acc[u][7] + r1.w);
            float* op = hdst_b + (c0 + u) * T_LEN + t0 + tt0;
            *reinterpret_cast<float4*>(op)     = a0;
            *reinterpret_cast<float4*>(op + 4) = a1;
        }
    }
}

// ---------------------------------------------------------------------------
// input 1x1 conv: h0[b,co,t] = b_in[co] + sum_ci w_in[co,ci] * x[b,ci,t]
// ---------------------------------------------------------------------------
__global__ void __launch_bounds__(256)
input_conv(const float* __restrict__ x, const float* __restrict__ w_in,
           const float* __restrict__ b_in)
{
    int gid = blockIdx.x * blockDim.x + threadIdx.x;   // 0 .. B*T-1
    int b = gid >> 12;          // T = 4096
    int t = gid & 4095;
    float xv[CH_IN];
    #pragma unroll
    for (int ci = 0; ci < CH_IN; ci++)
        xv[ci] = x[((size_t)b * CH_IN + ci) * T_LEN + t];
    float* h0 = &g_h[0][0] + (size_t)b * C_RES * T_LEN + t;
    #pragma unroll
    for (int co = 0; co < C_RES; co++) {
        float acc = __ldg(b_in + co);
        #pragma unroll
        for (int ci = 0; ci < CH_IN; ci++)
            acc = fmaf(__ldg(w_in + co * CH_IN + ci), xv[ci], acc);
        h0[(size_t)co * T_LEN] = acc;
    }
}

extern "C" void kernel_launch(void* const* d_in, const int* in_sizes, int n_in,
                              void* d_out, int out_size)
{
    (void)in_sizes; (void)n_in; (void)out_size;
    const float* x    = (const float*)d_in[0];
    const float* w_in = (const float*)d_in[1];
    const float* b_in = (const float*)d_in[2];
    const float* w_f  = (const float*)d_in[3];
    const float* b_f  = (const float*)d_in[4];
    const float* w_g  = (const float*)d_in[5];
    const float* b_g  = (const float*)d_in[6];
    const float* w_s  = (const float*)d_in[7];
    const float* b_s  = (const float*)d_in[8];
    const float* w_r  = (const float*)d_in[9];
    const float* b_r  = (const float*)d_in[10];
    float* skip = (float*)d_out;

    cudaFuncSetAttribute(wavenet_layer,
                         cudaFuncAttributeMaxDynamicSharedMemorySize, SMEM_BYTES);

    input_conv<<<(BATCH * T_LEN) / 256, 256>>>(x, w_in, b_in);

    for (int i = 0; i < NLAYERS; i++) {
        int dil = 1 << (i % 10);
        wavenet_layer<<<BATCH * (T_LEN / TILE_T), NTHREADS, SMEM_BYTES>>>(
            i & 1, i, dil, (i == 0) ? 1 : 0,
            w_f, b_f, w_g, b_g, w_s, b_s, w_r, b_r, skip);
    }
}

// round 13
// speedup vs baseline: 1.0051x; 1.0015x over previous
#include <cuda_runtime.h>
#include <math.h>

#define BATCH   32
#define T_LEN   4096
#define CH_IN   8
#define C_RES   64
#define C_SKIP  256
#define NLAYERS 20
#define TILE_T  128
#define NTHREADS 256

// ping-pong residual buffers: 2 x 32*64*4096 floats = 2 x 33.5 MB
__device__ float g_h[2][BATCH * C_RES * T_LEN];

// ---------------------------------------------------------------------------
// Shared memory layout (floats):
//   hc  [64][128]                     @ 0      (8192)
//   zz  [64][128]                     @ 8192   (8192)
//   regionX @ 16384:
//     phase A : wf0T/wf1T/wg0T/wg1T [64][64] (4*4096) then hp [64][128] (8192)
//     phase BC: wsT [64][256] (16384), wrT [64][64] (4096)
//   total = 16384 + 24576 = 40960 floats = 160 KB
// ---------------------------------------------------------------------------
#define SMEM_FLOATS 40960
#define SMEM_BYTES  (SMEM_FLOATS * 4)

__global__ void __launch_bounds__(NTHREADS, 1)
wavenet_layer(int ping, int layer, int dil, int first,
              const float* __restrict__ w_f, const float* __restrict__ b_f,
              const float* __restrict__ w_g, const float* __restrict__ b_g,
              const float* __restrict__ w_s, const float* __restrict__ b_s,
              const float* __restrict__ w_r, const float* __restrict__ b_r,
              float* __restrict__ skip_out)
{
    extern __shared__ float sm[];
    float* hc  = sm;                 // [64][128]
    float* zz  = sm + 8192;         // [64][128]
    float* wf0 = sm + 16384;        // [ci][co]  64x64
    float* wf1 = wf0 + 4096;
    float* wg0 = wf1 + 4096;
    float* wg1 = wg0 + 4096;
    float* hp  = wg1 + 4096;        // [64][128]
    float* wsT = sm + 16384;        // [ci][cs]  64x256  (phase B/C, overlays wf/hp)
    float* wrT = wsT + 16384;       // [ci][co]  64x64

    const int tid = threadIdx.x;
    const int blk = blockIdx.x;
    const int b   = blk / (T_LEN / TILE_T);
    const int t0  = (blk % (T_LEN / TILE_T)) * TILE_T;

    const float* __restrict__ hsrc_b = &g_h[ping][0]     + b * (C_RES * T_LEN);
    float*       __restrict__ hdst_b = &g_h[ping ^ 1][0] + b * (C_RES * T_LEN);

    // ---- load current h tile (vectorized, aligned: t0 % 128 == 0) ----
    #pragma unroll
    for (int k = 0; k < 8; k++) {
        int idx = tid + k * 256;        // float4 index, 0..2047
        int c   = idx >> 5;             // 32 float4 per 128-wide row
        int t4  = idx & 31;
        reinterpret_cast<float4*>(hc)[idx] =
            *(reinterpret_cast<const float4*>(hsrc_b + c * T_LEN + t0) + t4);
    }
    // ---- load dilated-past h tile (scalar: dil may be odd) ----
    #pragma unroll
    for (int k = 0; k < 32; k++) {
        int idx = tid + k * 256;        // 0..8191
        int c   = idx >> 7;
        int tt  = idx & 127;
        int tg  = t0 + tt - dil;
        hp[idx] = (tg >= 0) ? hsrc_b[c * T_LEN + tg] : 0.0f;
    }
    // ---- load f/g weights, transposed to [ci][co] ----
    {
        const float* wfb = w_f + layer * (C_RES * C_RES * 2);
        const float* wgb = w_g + layer * (C_RES * C_RES * 2);
        #pragma unroll
        for (int k = 0; k < 16; k++) {
            int e  = tid + k * 256;     // 0..4095
            int co = e >> 6, ci = e & 63;
            float2 vf = *reinterpret_cast<const float2*>(wfb + 2 * e);
            float2 vg = *reinterpret_cast<const float2*>(wgb + 2 * e);
            wf0[ci * 64 + co] = vf.x;  wf1[ci * 64 + co] = vf.y;
            wg0[ci * 64 + co] = vg.x;  wg1[ci * 64 + co] = vg.y;
        }
    }
    __syncthreads();

    const int tx  = tid & 15;
    const int ty  = tid >> 4;
    const int c0  = ty * 4;     // 4 output channels per thread
    const int tt0 = tx * 8;     // 8 timesteps per thread

    // =================== Phase A: gated pre-activations ====================
    float fa[4][8], ga[4][8];
    #pragma unroll
    for (int u = 0; u < 4; u++) {
        float bfv = b_f[layer * C_RES + c0 + u];
        float bgv = b_g[layer * C_RES + c0 + u];
        #pragma unroll
        for (int v = 0; v < 8; v++) { fa[u][v] = bfv; ga[u][v] = bgv; }
    }

    #pragma unroll 2
    for (int ci = 0; ci < 64; ci++) {
        float4 wA0 = *reinterpret_cast<float4*>(wf0 + ci * 64 + c0);
        float4 wA1 = *reinterpret_cast<float4*>(wf1 + ci * 64 + c0);
        float4 wB0 = *reinterpret_cast<float4*>(wg0 + ci * 64 + c0);
        float4 wB1 = *reinterpret_cast<float4*>(wg1 + ci * 64 + c0);
        float4 p0  = *reinterpret_cast<float4*>(hp + ci * 128 + tt0);
        float4 p1  = *reinterpret_cast<float4*>(hp + ci * 128 + tt0 + 4);
        float4 q0  = *reinterpret_cast<float4*>(hc + ci * 128 + tt0);
        float4 q1  = *reinterpret_cast<float4*>(hc + ci * 128 + tt0 + 4);

        float wf0v[4] = {wA0.x, wA0.y, wA0.z, wA0.w};
        float wf1v[4] = {wA1.x, wA1.y, wA1.z, wA1.w};
        float wg0v[4] = {wB0.x, wB0.y, wB0.z, wB0.w};
        float wg1v[4] = {wB1.x, wB1.y, wB1.z, wB1.w};
        float pv[8]   = {p0.x, p0.y, p0.z, p0.w, p1.x, p1.y, p1.z, p1.w};
        float cv[8]   = {q0.x, q0.y, q0.z, q0.w, q1.x, q1.y, q1.z, q1.w};

        #pragma unroll
        for (int u = 0; u < 4; u++)
            #pragma unroll
            for (int v = 0; v < 8; v++) {
                fa[u][v] = fmaf(wf0v[u], pv[v], fa[u][v]);
                fa[u][v] = fmaf(wf1v[u], cv[v], fa[u][v]);
                ga[u][v] = fmaf(wg0v[u], pv[v], ga[u][v]);
                ga[u][v] = fmaf(wg1v[u], cv[v], ga[u][v]);
            }
    }

    // ---- activations: z = tanh(f) * sigmoid(g) ----
    #pragma unroll
    for (int u = 0; u < 4; u++) {
        #pragma unroll
        for (int v = 0; v < 8; v++) {
            float f = fa[u][v], g = ga[u][v];
            float th = __fdividef(2.0f, 1.0f + __expf(-2.0f * f)) - 1.0f;
            float sg = __fdividef(1.0f, 1.0f + __expf(-g));
            fa[u][v] = th * sg;
        }
        float4 s0 = make_float4(fa[u][0], fa[u][1], fa[u][2], fa[u][3]);
        float4 s1 = make_float4(fa[u][4], fa[u][5], fa[u][6], fa[u][7]);
        *reinterpret_cast<float4*>(zz + (c0 + u) * 128 + tt0)     = s0;
        *reinterpret_cast<float4*>(zz + (c0 + u) * 128 + tt0 + 4) = s1;
    }
    __syncthreads();   // zz published; regionX reads done

    // ---- load skip / res weights, transposed ----
    {
        const float* wsb = w_s + layer * (C_SKIP * C_RES);
        #pragma unroll
        for (int k = 0; k < 64; k++) {
            int e  = tid + k * 256;     // 0..16383
            int cs = e >> 6, ci = e & 63;
            wsT[ci * 256 + cs] = wsb[e];
        }
        const float* wrb = w_r + layer * (C_RES * C_RES);
        #pragma unroll
        for (int k = 0; k < 16; k++) {
            int e  = tid + k * 256;
            int co = e >> 6, ci = e & 63;
            wrT[ci * 64 + co] = wrb[e];
        }
    }
    __syncthreads();

    // =================== Phase B: skip accumulation =========================
    #pragma unroll 1
    for (int q = 0; q < 4; q++) {
        const int cs0 = q * 64 + c0;
        float acc[4][8];
        #pragma unroll
        for (int u = 0; u < 4; u++) {
            float bsv = b_s[layer * C_SKIP + cs0 + u];
            #pragma unroll
            for (int v = 0; v < 8; v++) acc[u][v] = bsv;
        }
        #pragma unroll 2
        for (int ci = 0; ci < 64; ci++) {
            float4 wv = *reinterpret_cast<float4*>(wsT + ci * 256 + cs0);
            float4 z0 = *reinterpret_cast<float4*>(zz + ci * 128 + tt0);
            float4 z1 = *reinterpret_cast<float4*>(zz + ci * 128 + tt0 + 4);
            float wa[4] = {wv.x, wv.y, wv.z, wv.w};
            float zv[8] = {z0.x, z0.y, z0.z, z0.w, z1.x, z1.y, z1.z, z1.w};
            #pragma unroll
            for (int u = 0; u < 4; u++)
                #pragma unroll
                for (int v = 0; v < 8; v++)
                    acc[u][v] = fmaf(wa[u], zv[v], acc[u][v]);
        }
        #pragma unroll
        for (int u = 0; u < 4; u++) {
            float* op = skip_out + ((size_t)b * C_SKIP + cs0 + u) * T_LEN + t0 + tt0;
            float4 a0 = make_float4(acc[u][0], acc[u][1], acc[u][2], acc[u][3]);
            float4 a1 = make_float4(acc[u][4], acc[u][5], acc[u][6], acc[u][7]);
            if (first) {
                *reinterpret_cast<float4*>(op)     = a0;
                *reinterpret_cast<float4*>(op + 4) = a1;
            } else {
                float4 o0 = *reinterpret_cast<const float4*>(op);
                float4 o1 = *reinterpret_cast<const float4*>(op + 4);
                o0.x += a0.x; o0.y += a0.y; o0.z += a0.z; o0.w += a0.w;
                o1.x += a1.x; o1.y += a1.y; o1.z += a1.z; o1.w += a1.w;
                *reinterpret_cast<float4*>(op)     = o0;
                *reinterpret_cast<float4*>(op + 4) = o1;
            }
        }
    }

    // =================== Phase C: residual ==================================
    {
        float acc[4][8];
        #pragma unroll
        for (int u = 0; u < 4; u++) {
            float brv = b_r[layer * C_RES + c0 + u];
            #pragma unroll
            for (int v = 0; v < 8; v++) acc[u][v] = brv;
        }
        #pragma unroll 2
        for (int ci = 0; ci < 64; ci++) {
            float4 wv = *reinterpret_cast<float4*>(wrT + ci * 64 + c0);
            float4 z0 = *reinterpret_cast<float4*>(zz + ci * 128 + tt0);
            float4 z1 = *reinterpret_cast<float4*>(zz + ci * 128 + tt0 + 4);
            float wa[4] = {wv.x, wv.y, wv.z, wv.w};
            float zv[8] = {z0.x, z0.y, z0.z, z0.w, z1.x, z1.y, z1.z, z1.w};
            #pragma unroll
            for (int u = 0; u < 4; u++)
                #pragma unroll
                for (int v = 0; v < 8; v++)
                    acc[u][v] = fmaf(wa[u], zv[v], acc[u][v]);
        }
        #pragma unroll
        for (int u = 0; u < 4; u++) {
            float4 r0 = *reinterpret_cast<float4*>(hc + (c0 + u) * 128 + tt0);
            float4 r1 = *reinterpret_cast<float4*>(hc + (c0 + u) * 128 + tt0 + 4);
            float4 a0 = make_float4(acc[u][0] + r0.x, acc[u][1] + r0.y,
                                    acc[u][2] + r0.z, acc[u][3] + r0.w);
            float4 a1 = make_float4(acc[u][4] + r1.x, acc[u][5] + r1.y,
                                    acc[u][6] + r1.z, acc[u][7] + r1.w);
            float* op = hdst_b + (c0 + u) * T_LEN + t0 + tt0;
            *reinterpret_cast<float4*>(op)     = a0;
            *reinterpret_cast<float4*>(op + 4) = a1;
        }
    }
}

// ---------------------------------------------------------------------------
// input 1x1 conv: h0[b,co,t] = b_in[co] + sum_ci w_in[co,ci] * x[b,ci,t]
// ---------------------------------------------------------------------------
__global__ void __launch_bounds__(256)
input_conv(const float* __restrict__ x, const float* __restrict__ w_in,
           const float* __restrict__ b_in)
{
    int gid = blockIdx.x * blockDim.x + threadIdx.x;   // 0 .. B*T-1
    int b = gid >> 12;          // T = 4096
    int t = gid & 4095;
    float xv[CH_IN];
    #pragma unroll
    for (int ci = 0; ci < CH_IN; ci++)
        xv[ci] = x[((size_t)b * CH_IN + ci) * T_LEN + t];
    float* h0 = &g_h[0][0] + (size_t)b * C_RES * T_LEN + t;
    #pragma unroll
    for (int co = 0; co < C_RES; co++) {
        float acc = __ldg(b_in + co);
        #pragma unroll
        for (int ci = 0; ci < CH_IN; ci++)
            acc = fmaf(__ldg(w_in + co * CH_IN + ci), xv[ci], acc);
        h0[(size_t)co * T_LEN] = acc;
    }
}

extern "C" void kernel_launch(void* const* d_in, const int* in_sizes, int n_in,
                              void* d_out, int out_size)
{
    (void)in_sizes; (void)n_in; (void)out_size;
    const float* x    = (const float*)d_in[0];
    const float* w_in = (const float*)d_in[1];
    const float* b_in = (const float*)d_in[2];
    const float* w_f  = (const float*)d_in[3];
    const float* b_f  = (const float*)d_in[4];
    const float* w_g  = (const float*)d_in[5];
    const float* b_g  = (const float*)d_in[6];
    const float* w_s  = (const float*)d_in[7];
    const float* b_s  = (const float*)d_in[8];
    const float* w_r  = (const float*)d_in[9];
    const float* b_r  = (const float*)d_in[10];
    float* skip = (float*)d_out;

    cudaFuncSetAttribute(wavenet_layer,
                         cudaFuncAttributeMaxDynamicSharedMemorySize, SMEM_BYTES);

    input_conv<<<(BATCH * T_LEN) / 256, 256>>>(x, w_in, b_in);

    for (int i = 0; i < NLAYERS; i++) {
        int dil = 1 << (i % 10);
        wavenet_layer<<<BATCH * (T_LEN / TILE_T), NTHREADS, SMEM_BYTES>>>(
            i & 1, i, dil, (i == 0) ? 1 : 0,
            w_f, b_f, w_g, b_g, w_s, b_s, w_r, b_r, skip);
    }
}